// round 9
// baseline (speedup 1.0000x reference)
#include <cuda_runtime.h>
#include <math.h>

// EstimateAdj: out = diag(1/rowsum(A*B + I)) @ (A*B + I), N=8192.
// R9 (final policy cell): default cached loads + evict-first (.cs) stores.
//   - 1 row per CTA, 256 threads, 8x float4 per thread in registers
//     (inputs read once, output written once: 768 MB total = minimum)
//   - branch-free load loop; algebraic diagonal; single-barrier reduction
// Kernel is at the measured mixed read/write HBM ceiling (~6.9 TB/s).

#define N 8192
#define N4 (N / 4)            // 2048 float4 per row
#define TPB 256
#define V_PER_T (N4 / TPB)    // 8 float4 per thread
#define NWARPS (TPB / 32)     // 8

__device__ __forceinline__ void stcs4(float4* p, float4 v) {
    asm volatile("st.global.cs.v4.f32 [%0], {%1,%2,%3,%4};"
                 :: "l"(p), "f"(v.x), "f"(v.y), "f"(v.z), "f"(v.w) : "memory");
}

__global__ __launch_bounds__(TPB, 4)
void estimate_adj_kernel(const float4* __restrict__ A,
                         const float4* __restrict__ B,
                         float4* __restrict__ out) {
    const int row = blockIdx.x;
    const long base = (long)row * N4;
    const int tid = threadIdx.x;

    float4 p[V_PER_T];
    float sum = 0.0f;

    // Branch-free, front-batched coalesced loads (max MLP).
    #pragma unroll
    for (int j = 0; j < V_PER_T; j++) {
        const int idx = tid + j * TPB;   // 0..2047
        float4 a = A[base + idx];
        float4 b = B[base + idx];
        float4 m;
        m.x = a.x * b.x;
        m.y = a.y * b.y;
        m.z = a.z * b.z;
        m.w = a.w * b.w;
        p[j] = m;
        sum += (m.x + m.y) + (m.z + m.w);
    }

    // Warp reduction
    #pragma unroll
    for (int off = 16; off > 0; off >>= 1)
        sum += __shfl_xor_sync(0xFFFFFFFFu, sum, off);

    __shared__ float warp_sums[NWARPS];
    const int lane = tid & 31;
    const int wid = tid >> 5;
    if (lane == 0) warp_sums[wid] = sum;
    __syncthreads();

    // Every thread finishes the reduction itself (single barrier).
    // Identity contributes exactly +1 to every rowsum.
    float total = 1.0f;
    #pragma unroll
    for (int w = 0; w < NWARPS; w++) total += warp_sums[w];
    float rinv = 1.0f / total;
    if (isinf(rinv)) rinv = 0.0f;

    // Scale and store (evict-first); diagonal fixup: out[row][row] += rinv.
    const int diag4 = row >> 2;
    #pragma unroll
    for (int j = 0; j < V_PER_T; j++) {
        const int idx = tid + j * TPB;
        float4 m = p[j];
        m.x *= rinv; m.y *= rinv; m.z *= rinv; m.w *= rinv;
        if (idx == diag4) ((float*)&m)[row & 3] += rinv;
        stcs4(out + base + idx, m);
    }
}

extern "C" void kernel_launch(void* const* d_in, const int* in_sizes, int n_in,
                              void* d_out, int out_size) {
    const float4* A = (const float4*)d_in[0];   // estimated_adj
    const float4* B = (const float4*)d_in[1];   // ori
    float4* out = (float4*)d_out;
    estimate_adj_kernel<<<N, TPB>>>(A, B, out);
}

// round 10
// speedup vs baseline: 1.0027x; 1.0027x over previous
#include <cuda_runtime.h>
#include <math.h>

// EstimateAdj: out = diag(1/rowsum(A*B + I)) @ (A*B + I), N=8192.
// R10 (final): best-measured load path (ld.global.nc.L2::256B) + best-measured
// store path (st.global.wt) on the winning shape.
//   - 1 row per CTA, 256 threads, 8x float4 per thread in registers
//     (inputs read once, output written once: 768 MB = provable minimum)
//   - branch-free load loop; algebraic diagonal; single-barrier reduction
// Kernel sits at the measured mixed read/write HBM ceiling (~6.9 TB/s).

#define N 8192
#define N4 (N / 4)            // 2048 float4 per row
#define TPB 256
#define V_PER_T (N4 / TPB)    // 8 float4 per thread
#define NWARPS (TPB / 32)     // 8

__device__ __forceinline__ float4 ldg256(const float4* p) {
    float4 v;
    asm volatile("ld.global.nc.L2::256B.v4.f32 {%0,%1,%2,%3}, [%4];"
                 : "=f"(v.x), "=f"(v.y), "=f"(v.z), "=f"(v.w) : "l"(p));
    return v;
}

__device__ __forceinline__ void stwt4(float4* p, float4 v) {
    asm volatile("st.global.wt.v4.f32 [%0], {%1,%2,%3,%4};"
                 :: "l"(p), "f"(v.x), "f"(v.y), "f"(v.z), "f"(v.w) : "memory");
}

__global__ __launch_bounds__(TPB, 4)
void estimate_adj_kernel(const float4* __restrict__ A,
                         const float4* __restrict__ B,
                         float4* __restrict__ out) {
    const int row = blockIdx.x;
    const long base = (long)row * N4;
    const int tid = threadIdx.x;

    float4 p[V_PER_T];
    float sum = 0.0f;

    // Branch-free, front-batched coalesced loads (max MLP, 256B L2 sectors).
    #pragma unroll
    for (int j = 0; j < V_PER_T; j++) {
        const int idx = tid + j * TPB;   // 0..2047
        float4 a = ldg256(A + base + idx);
        float4 b = ldg256(B + base + idx);
        float4 m;
        m.x = a.x * b.x;
        m.y = a.y * b.y;
        m.z = a.z * b.z;
        m.w = a.w * b.w;
        p[j] = m;
        sum += (m.x + m.y) + (m.z + m.w);
    }

    // Warp reduction
    #pragma unroll
    for (int off = 16; off > 0; off >>= 1)
        sum += __shfl_xor_sync(0xFFFFFFFFu, sum, off);

    __shared__ float warp_sums[NWARPS];
    const int lane = tid & 31;
    const int wid = tid >> 5;
    if (lane == 0) warp_sums[wid] = sum;
    __syncthreads();

    // Every thread finishes the reduction itself (single barrier).
    // Identity contributes exactly +1 to every rowsum.
    float total = 1.0f;
    #pragma unroll
    for (int w = 0; w < NWARPS; w++) total += warp_sums[w];
    float rinv = 1.0f / total;
    if (isinf(rinv)) rinv = 0.0f;

    // Scale and store (write-through); diagonal fixup: out[row][row] += rinv.
    const int diag4 = row >> 2;
    #pragma unroll
    for (int j = 0; j < V_PER_T; j++) {
        const int idx = tid + j * TPB;
        float4 m = p[j];
        m.x *= rinv; m.y *= rinv; m.z *= rinv; m.w *= rinv;
        if (idx == diag4) ((float*)&m)[row & 3] += rinv;
        stwt4(out + base + idx, m);
    }
}

extern "C" void kernel_launch(void* const* d_in, const int* in_sizes, int n_in,
                              void* d_out, int out_size) {
    const float4* A = (const float4*)d_in[0];   // estimated_adj
    const float4* B = (const float4*)d_in[1];   // ori
    float4* out = (float4*)d_out;
    estimate_adj_kernel<<<N, TPB>>>(A, B, out);
}

// round 11
// speedup vs baseline: 1.0115x; 1.0087x over previous
#include <cuda_runtime.h>
#include <math.h>

// EstimateAdj: out = diag(1/rowsum(A*B + I)) @ (A*B + I), N=8192.
// FINAL (= R2, best benched variant of the session at 117.2us):
//   - single pass: inputs read exactly once, output written exactly once
//     (768 MB total = provable minimum traffic)
//   - 1 row per CTA, 512 threads x 4 float4 held in registers
//   - reg-capped (40 regs) for 3 CTAs/SM -> ~69% occupancy
//   - single-barrier block reduction (every thread folds the 16 partials)
// Measured at ~6.85 TB/s = the chip's mixed read/write HBM ceiling; all
// occupancy / cache-policy / fusion / persistence levers verified neutral.

#define N 8192
#define N4 (N / 4)            // 2048 float4 per row
#define TPB 512
#define V_PER_T (N4 / TPB)    // 4 float4 per thread
#define NWARPS (TPB / 32)     // 16

__global__ __launch_bounds__(TPB, 3)
void estimate_adj_kernel(const float4* __restrict__ A,
                         const float4* __restrict__ B,
                         float4* __restrict__ out) {
    const int row = blockIdx.x;
    const long base = (long)row * N4;
    const int tid = threadIdx.x;
    const int diag4 = row >> 2;          // float4 index of the diagonal element

    float4 p[V_PER_T];
    float sum = 0.0f;

    // Load + multiply + diagonal injection. Coalesced, front-batched loads.
    #pragma unroll
    for (int j = 0; j < V_PER_T; j++) {
        const int idx = tid + j * TPB;   // 0..2047
        float4 a = A[base + idx];
        float4 b = B[base + idx];
        float4 m;
        m.x = a.x * b.x;
        m.y = a.y * b.y;
        m.z = a.z * b.z;
        m.w = a.w * b.w;
        if (idx == diag4) {
            ((float*)&m)[row & 3] += 1.0f;
        }
        p[j] = m;
        sum += (m.x + m.y) + (m.z + m.w);
    }

    // Warp reduction
    #pragma unroll
    for (int off = 16; off > 0; off >>= 1)
        sum += __shfl_xor_sync(0xFFFFFFFFu, sum, off);

    __shared__ float warp_sums[NWARPS];
    const int lane = tid & 31;
    const int wid = tid >> 5;
    if (lane == 0) warp_sums[wid] = sum;
    __syncthreads();

    // Every thread finishes the reduction itself (no second barrier).
    float total = 0.0f;
    #pragma unroll
    for (int w = 0; w < NWARPS; w++) total += warp_sums[w];
    float rinv = 1.0f / total;
    if (isinf(rinv)) rinv = 0.0f;

    // Scale and store from registers.
    #pragma unroll
    for (int j = 0; j < V_PER_T; j++) {
        const int idx = tid + j * TPB;
        float4 m = p[j];
        m.x *= rinv; m.y *= rinv; m.z *= rinv; m.w *= rinv;
        out[base + idx] = m;
    }
}

extern "C" void kernel_launch(void* const* d_in, const int* in_sizes, int n_in,
                              void* d_out, int out_size) {
    const float4* A = (const float4*)d_in[0];   // estimated_adj
    const float4* B = (const float4*)d_in[1];   // ori
    float4* out = (float4*)d_out;
    estimate_adj_kernel<<<N, TPB>>>(A, B, out);
}

// round 12
// speedup vs baseline: 1.0153x; 1.0038x over previous
#include <cuda_runtime.h>
#include <math.h>

// EstimateAdj: out = diag(1/rowsum(A*B + I)) @ (A*B + I), N=8192.
// R12: full-occupancy cell. 1 row per CTA, 1024 threads x 2 float4 in regs,
//     2 CTAs/SM = 64 warps = 100% occupancy (last unmeasured shape).
//   - single pass (768 MB = minimum traffic)
//   - branch-free load loop; algebraic diagonal; single-barrier reduction

#define N 8192
#define N4 (N / 4)            // 2048 float4 per row
#define TPB 1024
#define V_PER_T (N4 / TPB)    // 2 float4 per thread
#define NWARPS (TPB / 32)     // 32

__global__ __launch_bounds__(TPB, 2)
void estimate_adj_kernel(const float4* __restrict__ A,
                         const float4* __restrict__ B,
                         float4* __restrict__ out) {
    const int row = blockIdx.x;
    const long base = (long)row * N4;
    const int tid = threadIdx.x;

    float4 p[V_PER_T];
    float sum = 0.0f;

    // Branch-free, front-batched coalesced loads.
    #pragma unroll
    for (int j = 0; j < V_PER_T; j++) {
        const int idx = tid + j * TPB;   // 0..2047
        float4 a = A[base + idx];
        float4 b = B[base + idx];
        float4 m;
        m.x = a.x * b.x;
        m.y = a.y * b.y;
        m.z = a.z * b.z;
        m.w = a.w * b.w;
        p[j] = m;
        sum += (m.x + m.y) + (m.z + m.w);
    }

    // Warp reduction
    #pragma unroll
    for (int off = 16; off > 0; off >>= 1)
        sum += __shfl_xor_sync(0xFFFFFFFFu, sum, off);

    __shared__ float warp_sums[NWARPS];
    const int lane = tid & 31;
    const int wid = tid >> 5;
    if (lane == 0) warp_sums[wid] = sum;
    __syncthreads();

    // Every thread finishes the reduction itself (single barrier).
    // Identity contributes exactly +1 to every rowsum.
    float total = 1.0f;
    #pragma unroll
    for (int w = 0; w < NWARPS; w++) total += warp_sums[w];
    float rinv = 1.0f / total;
    if (isinf(rinv)) rinv = 0.0f;

    // Scale and store from registers; diagonal fixup: out[row][row] += rinv.
    const int diag4 = row >> 2;
    #pragma unroll
    for (int j = 0; j < V_PER_T; j++) {
        const int idx = tid + j * TPB;
        float4 m = p[j];
        m.x *= rinv; m.y *= rinv; m.z *= rinv; m.w *= rinv;
        if (idx == diag4) ((float*)&m)[row & 3] += rinv;
        out[base + idx] = m;
    }
}

extern "C" void kernel_launch(void* const* d_in, const int* in_sizes, int n_in,
                              void* d_out, int out_size) {
    const float4* A = (const float4*)d_in[0];   // estimated_adj
    const float4* B = (const float4*)d_in[1];   // ori
    float4* out = (float4*)d_out;
    estimate_adj_kernel<<<N, TPB>>>(A, B, out);
}